// round 10
// baseline (speedup 1.0000x reference)
#include <cuda_runtime.h>

#define HIDDEN 128
#define NTYPES 28
#define MAX_CYCLES 500000

// Packed per-cycle type histogram: 2 x u64, 16 types/word, 4-bit nibbles
// (word = t>>4, nibble = t&15; nibbles 28-31 never touched).
// Zero at module load; k_final self-cleans after reading, so every replay
// sees zeros. Integer red-adds => deterministic.
__device__ ulonglong2 g_hist[MAX_CYCLES];   // 8 MB, L2-resident

// ---------------------------------------------------------------------------
// Scatter: one red.global.add.u64 per incidence (no return, no cursor).
// ---------------------------------------------------------------------------
__global__ void __launch_bounds__(256)
k_scatter(const int* __restrict__ x,
          const int* __restrict__ atom_row,
          const int* __restrict__ cyc_row, int n)
{
    const int n4 = n >> 2;
    int i = blockIdx.x * blockDim.x + threadIdx.x;
    const int stride = gridDim.x * blockDim.x;
    const int4* a4 = reinterpret_cast<const int4*>(atom_row);
    const int4* c4 = reinterpret_cast<const int4*>(cyc_row);

    for (; i < n4; i += stride) {
        int4 a = __ldg(&a4[i]);
        int4 c = __ldg(&c4[i]);
        int atoms[4] = {a.x, a.y, a.z, a.w};
        int cycs[4]  = {c.x, c.y, c.z, c.w};
#pragma unroll
        for (int k = 0; k < 4; k++) {
            int t = __ldg(&x[atoms[k]]);
            unsigned long long inc = 1ULL << ((t & 15) * 4);
            unsigned long long* dst =
                reinterpret_cast<unsigned long long*>(&g_hist[cycs[k]]) + (t >> 4);
            asm volatile("red.global.add.u64 [%0], %1;"
                         :: "l"(dst), "l"(inc) : "memory");
        }
    }
    for (int j = (n4 << 2) + blockIdx.x * blockDim.x + threadIdx.x; j < n;
         j += stride) {
        int t = __ldg(&x[__ldg(&atom_row[j])]);
        int cyc = __ldg(&cyc_row[j]);
        unsigned long long inc = 1ULL << ((t & 15) * 4);
        unsigned long long* dst =
            reinterpret_cast<unsigned long long*>(&g_hist[cyc]) + (t >> 4);
        asm volatile("red.global.add.u64 [%0], %1;"
                     :: "l"(dst), "l"(inc) : "memory");
    }
}

// ---------------------------------------------------------------------------
// Final: one warp per FOUR consecutive cycles. Lane l extracts count of
// type l from each hist; ONE ballot over the union of present types; per
// union type: one LDS.128 of E[t], 4 shuffled counts (0 if absent -> FMA
// adds 0, exact), 8 fma.rn.f32x2. Four coalesced 512 B stores, one
// coalesced 64 B hist self-clean per batch.
// ---------------------------------------------------------------------------
__device__ __forceinline__ unsigned extract_cnt(uint4 h, int lane)
{
    // types 0-7 -> h.x, 8-15 -> h.y, 16-23 -> h.z, 24-27 -> h.w
    unsigned lo16 = (lane & 8)  ? h.y : h.x;
    unsigned hi16 = (lane & 8)  ? h.w : h.z;
    unsigned w    = (lane & 16) ? hi16 : lo16;
    return (w >> ((lane & 7) * 4)) & 0xFu;
}

__device__ __forceinline__ void fma2(unsigned long long& acc,
                                     unsigned long long v,
                                     unsigned long long fc2)
{
    asm("fma.rn.f32x2 %0, %1, %2, %0;" : "+l"(acc) : "l"(v), "l"(fc2));
}

__device__ __forceinline__ unsigned long long pack2(float f)
{
    unsigned long long r;
    asm("mov.b64 %0, {%1, %1};" : "=l"(r) : "f"(f));
    return r;
}

// single-row path (tail only; executed warp-uniformly)
__device__ __forceinline__ void accum_one(uint4 h, int lane,
                                          const float4* s_emb,
                                          unsigned long long& a,
                                          unsigned long long& b)
{
    unsigned cnt = extract_cnt(h, lane);
    float fcnt = (float)cnt;
    unsigned mask = __ballot_sync(0xFFFFFFFFu, cnt != 0u);
    while (mask) {
        int t = __ffs(mask) - 1;
        mask &= mask - 1;
        unsigned long long fc2 = pack2(__shfl_sync(0xFFFFFFFFu, fcnt, t));
        ulonglong2 v = *reinterpret_cast<const ulonglong2*>(&s_emb[t * 32 + lane]);
        fma2(a, v.x, fc2); fma2(b, v.y, fc2);
    }
}

__global__ void __launch_bounds__(256)
k_final(const float* __restrict__ emb, float* __restrict__ out, int ncyc)
{
    __shared__ float4 s_emb[NTYPES * 32];
    for (int i = threadIdx.x; i < NTYPES * 32; i += blockDim.x)
        s_emb[i] = reinterpret_cast<const float4*>(emb)[i];
    __syncthreads();

    const int lane = threadIdx.x & 31;
    const int warp = (blockIdx.x * blockDim.x + threadIdx.x) >> 5;
    const int nw   = (gridDim.x * blockDim.x) >> 5;
    ulonglong2* out2 = reinterpret_cast<ulonglong2*>(out);
    const uint4* hist4 = reinterpret_cast<const uint4*>(g_hist);
    const ulonglong2 zero2 = make_ulonglong2(0ULL, 0ULL);

    for (int c0 = warp * 4; c0 < ncyc; c0 += 4 * nw) {
        if (c0 + 3 < ncyc) {
            // ---- fast path: 4 rows, union type mask ----
            uint4 h0 = __ldg(&hist4[c0]);
            uint4 h1 = __ldg(&hist4[c0 + 1]);
            uint4 h2 = __ldg(&hist4[c0 + 2]);
            uint4 h3 = __ldg(&hist4[c0 + 3]);

            unsigned n0 = extract_cnt(h0, lane);
            unsigned n1 = extract_cnt(h1, lane);
            unsigned n2 = extract_cnt(h2, lane);
            unsigned n3 = extract_cnt(h3, lane);
            float f0 = (float)n0, f1 = (float)n1, f2 = (float)n2, f3 = (float)n3;

            unsigned mask = __ballot_sync(0xFFFFFFFFu, (n0 | n1 | n2 | n3) != 0u);

            unsigned long long a0 = 0, b0 = 0, a1 = 0, b1 = 0;
            unsigned long long a2 = 0, b2 = 0, a3 = 0, b3 = 0;

            while (mask) {
                int t = __ffs(mask) - 1;
                mask &= mask - 1;
                unsigned long long g0 = pack2(__shfl_sync(0xFFFFFFFFu, f0, t));
                unsigned long long g1 = pack2(__shfl_sync(0xFFFFFFFFu, f1, t));
                unsigned long long g2 = pack2(__shfl_sync(0xFFFFFFFFu, f2, t));
                unsigned long long g3 = pack2(__shfl_sync(0xFFFFFFFFu, f3, t));
                ulonglong2 v =
                    *reinterpret_cast<const ulonglong2*>(&s_emb[t * 32 + lane]);
                fma2(a0, v.x, g0); fma2(b0, v.y, g0);
                fma2(a1, v.x, g1); fma2(b1, v.y, g1);
                fma2(a2, v.x, g2); fma2(b2, v.y, g2);
                fma2(a3, v.x, g3); fma2(b3, v.y, g3);
            }

            size_t base = (size_t)c0 * 32 + lane;
            out2[base]      = make_ulonglong2(a0, b0);
            out2[base + 32] = make_ulonglong2(a1, b1);
            out2[base + 64] = make_ulonglong2(a2, b2);
            out2[base + 96] = make_ulonglong2(a3, b3);

            // coalesced 64 B self-clean
            if (lane < 4) g_hist[c0 + lane] = zero2;
        } else {
            // ---- tail: per-row, warp-uniform guards ----
            for (int j = 0; j < 4; j++) {
                int c = c0 + j;
                if (c < ncyc) {
                    uint4 h = __ldg(&hist4[c]);
                    unsigned long long a = 0, b = 0;
                    accum_one(h, lane, s_emb, a, b);
                    out2[(size_t)c * 32 + lane] = make_ulonglong2(a, b);
                    if (lane == 0) g_hist[c] = zero2;
                }
            }
        }
    }
}

// ---------------------------------------------------------------------------
// Inputs (metadata order):
//   d_in[0]: x             int32 [500000]
//   d_in[1]: atom_to_cycle int32 [2, 2000000]  (row 0 = atom idx, row 1 = cycle idx)
//   d_in[2]: emb_weight    fp32  [28, 128]
// Output: fp32 [500000, 128]
// ---------------------------------------------------------------------------
extern "C" void kernel_launch(void* const* d_in, const int* in_sizes, int n_in,
                              void* d_out, int out_size)
{
    const int*   x   = (const int*)d_in[0];
    const int*   a2c = (const int*)d_in[1];
    const float* emb = (const float*)d_in[2];
    float*       out = (float*)d_out;

    const int n_inc = in_sizes[1] / 2;
    const int ncyc  = out_size / HIDDEN;

    k_scatter<<<1184, 256>>>(x, a2c, a2c + n_inc, n_inc);
    k_final<<<1184, 256>>>(emb, out, ncyc);
}

// round 11
// speedup vs baseline: 1.0228x; 1.0228x over previous
#include <cuda_runtime.h>

#define HIDDEN 128
#define NTYPES 28
#define MAX_CYCLES 500000

// Packed per-cycle type histogram: 2 x u64, 16 types/word, 4-bit nibbles
// (word = t>>4, nibble = t&15; nibbles 28-31 never touched).
// Zero at module load; k_final self-cleans after reading, so every replay
// sees zeros. Integer red-adds => deterministic.
__device__ ulonglong2 g_hist[MAX_CYCLES];   // 8 MB, L2-resident

// ---------------------------------------------------------------------------
// Scatter: one red.global.add.u64 per incidence (no return, no cursor).
// ---------------------------------------------------------------------------
__global__ void __launch_bounds__(256)
k_scatter(const int* __restrict__ x,
          const int* __restrict__ atom_row,
          const int* __restrict__ cyc_row, int n)
{
    const int n4 = n >> 2;
    int i = blockIdx.x * blockDim.x + threadIdx.x;
    const int stride = gridDim.x * blockDim.x;
    const int4* a4 = reinterpret_cast<const int4*>(atom_row);
    const int4* c4 = reinterpret_cast<const int4*>(cyc_row);

    for (; i < n4; i += stride) {
        int4 a = __ldg(&a4[i]);
        int4 c = __ldg(&c4[i]);
        int atoms[4] = {a.x, a.y, a.z, a.w};
        int cycs[4]  = {c.x, c.y, c.z, c.w};
#pragma unroll
        for (int k = 0; k < 4; k++) {
            int t = __ldg(&x[atoms[k]]);
            unsigned long long inc = 1ULL << ((t & 15) * 4);
            unsigned long long* dst =
                reinterpret_cast<unsigned long long*>(&g_hist[cycs[k]]) + (t >> 4);
            asm volatile("red.global.add.u64 [%0], %1;"
                         :: "l"(dst), "l"(inc) : "memory");
        }
    }
    for (int j = (n4 << 2) + blockIdx.x * blockDim.x + threadIdx.x; j < n;
         j += stride) {
        int t = __ldg(&x[__ldg(&atom_row[j])]);
        int cyc = __ldg(&cyc_row[j]);
        unsigned long long inc = 1ULL << ((t & 15) * 4);
        unsigned long long* dst =
            reinterpret_cast<unsigned long long*>(&g_hist[cyc]) + (t >> 4);
        asm volatile("red.global.add.u64 [%0], %1;"
                     :: "l"(dst), "l"(inc) : "memory");
    }
}

// ---------------------------------------------------------------------------
// Final: one warp per FOUR consecutive cycles. Lane l holds the 4 per-row
// counts of type l packed as BYTES in one u32; one ballot over the union of
// present types; per union type: ONE shfl of the packed counts, 4x byte
// extract+I2F, one LDS.128 of E[t], 8 fma.rn.f32x2. Four coalesced 512 B
// stores + one coalesced 64 B hist self-clean per batch.
// ---------------------------------------------------------------------------
__device__ __forceinline__ unsigned extract_cnt(uint4 h, int lane)
{
    // types 0-7 -> h.x, 8-15 -> h.y, 16-23 -> h.z, 24-27 -> h.w
    unsigned lo16 = (lane & 8)  ? h.y : h.x;
    unsigned hi16 = (lane & 8)  ? h.w : h.z;
    unsigned w    = (lane & 16) ? hi16 : lo16;
    return (w >> ((lane & 7) * 4)) & 0xFu;
}

__device__ __forceinline__ void fma2(unsigned long long& acc,
                                     unsigned long long v,
                                     unsigned long long fc2)
{
    asm("fma.rn.f32x2 %0, %1, %2, %0;" : "+l"(acc) : "l"(v), "l"(fc2));
}

__device__ __forceinline__ unsigned long long pack2(float f)
{
    unsigned long long r;
    asm("mov.b64 %0, {%1, %1};" : "=l"(r) : "f"(f));
    return r;
}

// single-row path (tail only; executed warp-uniformly)
__device__ __forceinline__ void accum_one(uint4 h, int lane,
                                          const float4* s_emb,
                                          unsigned long long& a,
                                          unsigned long long& b)
{
    unsigned cnt = extract_cnt(h, lane);
    float fcnt = (float)cnt;
    unsigned mask = __ballot_sync(0xFFFFFFFFu, cnt != 0u);
    while (mask) {
        int t = __ffs(mask) - 1;
        mask &= mask - 1;
        unsigned long long fc2 = pack2(__shfl_sync(0xFFFFFFFFu, fcnt, t));
        ulonglong2 v = *reinterpret_cast<const ulonglong2*>(&s_emb[t * 32 + lane]);
        fma2(a, v.x, fc2); fma2(b, v.y, fc2);
    }
}

__global__ void __launch_bounds__(256)
k_final(const float* __restrict__ emb, float* __restrict__ out, int ncyc)
{
    __shared__ float4 s_emb[NTYPES * 32];
    for (int i = threadIdx.x; i < NTYPES * 32; i += blockDim.x)
        s_emb[i] = reinterpret_cast<const float4*>(emb)[i];
    __syncthreads();

    const int lane = threadIdx.x & 31;
    const int warp = (blockIdx.x * blockDim.x + threadIdx.x) >> 5;
    const int nw   = (gridDim.x * blockDim.x) >> 5;
    ulonglong2* out2 = reinterpret_cast<ulonglong2*>(out);
    const uint4* hist4 = reinterpret_cast<const uint4*>(g_hist);
    const ulonglong2 zero2 = make_ulonglong2(0ULL, 0ULL);

    for (int c0 = warp * 4; c0 < ncyc; c0 += 4 * nw) {
        if (c0 + 3 < ncyc) {
            // ---- fast path: 4 rows, union type mask, byte-packed counts ----
            uint4 h0 = __ldg(&hist4[c0]);
            uint4 h1 = __ldg(&hist4[c0 + 1]);
            uint4 h2 = __ldg(&hist4[c0 + 2]);
            uint4 h3 = __ldg(&hist4[c0 + 3]);

            unsigned n0 = extract_cnt(h0, lane);
            unsigned n1 = extract_cnt(h1, lane);
            unsigned n2 = extract_cnt(h2, lane);
            unsigned n3 = extract_cnt(h3, lane);
            unsigned pk = n0 | (n1 << 8) | (n2 << 16) | (n3 << 24);

            unsigned mask = __ballot_sync(0xFFFFFFFFu, pk != 0u);

            unsigned long long a0 = 0, b0 = 0, a1 = 0, b1 = 0;
            unsigned long long a2 = 0, b2 = 0, a3 = 0, b3 = 0;

            while (mask) {
                int t = __ffs(mask) - 1;
                mask &= mask - 1;
                unsigned v = __shfl_sync(0xFFFFFFFFu, pk, t);   // ONE shfl
                unsigned long long g0 = pack2((float)(v & 0xFFu));
                unsigned long long g1 = pack2((float)((v >> 8) & 0xFFu));
                unsigned long long g2 = pack2((float)((v >> 16) & 0xFFu));
                unsigned long long g3 = pack2((float)(v >> 24));
                ulonglong2 e =
                    *reinterpret_cast<const ulonglong2*>(&s_emb[t * 32 + lane]);
                fma2(a0, e.x, g0); fma2(b0, e.y, g0);
                fma2(a1, e.x, g1); fma2(b1, e.y, g1);
                fma2(a2, e.x, g2); fma2(b2, e.y, g2);
                fma2(a3, e.x, g3); fma2(b3, e.y, g3);
            }

            size_t base = (size_t)c0 * 32 + lane;
            out2[base]      = make_ulonglong2(a0, b0);
            out2[base + 32] = make_ulonglong2(a1, b1);
            out2[base + 64] = make_ulonglong2(a2, b2);
            out2[base + 96] = make_ulonglong2(a3, b3);

            // coalesced 64 B self-clean
            if (lane < 4) g_hist[c0 + lane] = zero2;
        } else {
            // ---- tail: per-row, warp-uniform guards ----
            for (int j = 0; j < 4; j++) {
                int c = c0 + j;
                if (c < ncyc) {
                    uint4 h = __ldg(&hist4[c]);
                    unsigned long long a = 0, b = 0;
                    accum_one(h, lane, s_emb, a, b);
                    out2[(size_t)c * 32 + lane] = make_ulonglong2(a, b);
                    if (lane == 0) g_hist[c] = zero2;
                }
            }
        }
    }
}

// ---------------------------------------------------------------------------
// Inputs (metadata order):
//   d_in[0]: x             int32 [500000]
//   d_in[1]: atom_to_cycle int32 [2, 2000000]  (row 0 = atom idx, row 1 = cycle idx)
//   d_in[2]: emb_weight    fp32  [28, 128]
// Output: fp32 [500000, 128]
// ---------------------------------------------------------------------------
extern "C" void kernel_launch(void* const* d_in, const int* in_sizes, int n_in,
                              void* d_out, int out_size)
{
    const int*   x   = (const int*)d_in[0];
    const int*   a2c = (const int*)d_in[1];
    const float* emb = (const float*)d_in[2];
    float*       out = (float*)d_out;

    const int n_inc = in_sizes[1] / 2;
    const int ncyc  = out_size / HIDDEN;

    k_scatter<<<1184, 256>>>(x, a2c, a2c + n_inc, n_inc);
    k_final<<<1184, 256>>>(emb, out, ncyc);
}

// round 12
// speedup vs baseline: 1.0727x; 1.0488x over previous
#include <cuda_runtime.h>

#define HIDDEN 128
#define NTYPES 28
#define MAX_CYCLES 500000

// Packed per-cycle type histogram: 2 x u64, 16 types/word, 4-bit nibbles
// (word = t>>4, nibble = t&15; nibbles 28-31 never touched).
// Zero at module load; k_final self-cleans after reading, so every replay
// sees zeros. Integer red-adds => deterministic.
__device__ ulonglong2 g_hist[MAX_CYCLES];   // 8 MB, L2-resident

// ---------------------------------------------------------------------------
// Scatter: one red.global.add.u64 per incidence (no return, no cursor).
// ---------------------------------------------------------------------------
__global__ void __launch_bounds__(256)
k_scatter(const int* __restrict__ x,
          const int* __restrict__ atom_row,
          const int* __restrict__ cyc_row, int n)
{
    const int n4 = n >> 2;
    int i = blockIdx.x * blockDim.x + threadIdx.x;
    const int stride = gridDim.x * blockDim.x;
    const int4* a4 = reinterpret_cast<const int4*>(atom_row);
    const int4* c4 = reinterpret_cast<const int4*>(cyc_row);

    for (; i < n4; i += stride) {
        int4 a = __ldg(&a4[i]);
        int4 c = __ldg(&c4[i]);
        int atoms[4] = {a.x, a.y, a.z, a.w};
        int cycs[4]  = {c.x, c.y, c.z, c.w};
#pragma unroll
        for (int k = 0; k < 4; k++) {
            int t = __ldg(&x[atoms[k]]);
            unsigned long long inc = 1ULL << ((t & 15) * 4);
            unsigned long long* dst =
                reinterpret_cast<unsigned long long*>(&g_hist[cycs[k]]) + (t >> 4);
            asm volatile("red.global.add.u64 [%0], %1;"
                         :: "l"(dst), "l"(inc) : "memory");
        }
    }
    for (int j = (n4 << 2) + blockIdx.x * blockDim.x + threadIdx.x; j < n;
         j += stride) {
        int t = __ldg(&x[__ldg(&atom_row[j])]);
        int cyc = __ldg(&cyc_row[j]);
        unsigned long long inc = 1ULL << ((t & 15) * 4);
        unsigned long long* dst =
            reinterpret_cast<unsigned long long*>(&g_hist[cyc]) + (t >> 4);
        asm volatile("red.global.add.u64 [%0], %1;"
                     :: "l"(dst), "l"(inc) : "memory");
    }
}

// ---------------------------------------------------------------------------
// Final: one warp per cycle, ILP-2, software-pipelined hist prefetch.
// Lane l extracts count of type l; ballot -> sparse type mask; per set bit:
// shfl count, LDS.128 of fp32 E[t] slice, 2x fma.rn.f32x2. One coalesced
// 512 B store per cycle; self-clean hist afterwards.
// ---------------------------------------------------------------------------
__device__ __forceinline__ unsigned extract_cnt(uint4 h, int lane)
{
    unsigned lo16 = (lane & 8)  ? h.y : h.x;
    unsigned hi16 = (lane & 8)  ? h.w : h.z;
    unsigned w    = (lane & 16) ? hi16 : lo16;
    return (w >> ((lane & 7) * 4)) & 0xFu;
}

__device__ __forceinline__ void fma2(unsigned long long& acc,
                                     unsigned long long v,
                                     unsigned long long fc2)
{
    asm("fma.rn.f32x2 %0, %1, %2, %0;" : "+l"(acc) : "l"(v), "l"(fc2));
}

__device__ __forceinline__ unsigned long long pack2(float f)
{
    unsigned long long r;
    asm("mov.b64 %0, {%1, %1};" : "=l"(r) : "f"(f));
    return r;
}

__device__ __forceinline__ void accum_cycle(uint4 h, int lane,
                                            const float4* s_emb,
                                            unsigned long long& a,
                                            unsigned long long& b)
{
    unsigned cnt = extract_cnt(h, lane);
    float fcnt = (float)cnt;
    unsigned mask = __ballot_sync(0xFFFFFFFFu, cnt != 0u);
    while (mask) {
        int t = __ffs(mask) - 1;
        mask &= mask - 1;
        unsigned long long fc2 = pack2(__shfl_sync(0xFFFFFFFFu, fcnt, t));
        ulonglong2 v = *reinterpret_cast<const ulonglong2*>(&s_emb[t * 32 + lane]);
        fma2(a, v.x, fc2); fma2(b, v.y, fc2);
    }
}

__global__ void __launch_bounds__(256)
k_final(const float* __restrict__ emb, float* __restrict__ out, int ncyc)
{
    __shared__ float4 s_emb[NTYPES * 32];
    for (int i = threadIdx.x; i < NTYPES * 32; i += blockDim.x)
        s_emb[i] = reinterpret_cast<const float4*>(emb)[i];
    __syncthreads();

    const int lane = threadIdx.x & 31;
    const int warp = (blockIdx.x * blockDim.x + threadIdx.x) >> 5;
    const int nw   = (gridDim.x * blockDim.x) >> 5;
    ulonglong2* out2 = reinterpret_cast<ulonglong2*>(out);
    const uint4* hist4 = reinterpret_cast<const uint4*>(g_hist);
    const ulonglong2 zero2 = make_ulonglong2(0ULL, 0ULL);
    const uint4 zero4 = make_uint4(0, 0, 0, 0);

    int c = warp;
    uint4 h1 = (c      < ncyc) ? __ldg(&hist4[c])      : zero4;
    uint4 h2 = (c + nw < ncyc) ? __ldg(&hist4[c + nw]) : zero4;

    while (c < ncyc) {
        const int cn = c + 2 * nw;
        // Prefetch next pair: their L2 latency overlaps this pair's work.
        uint4 p1 = (cn      < ncyc) ? __ldg(&hist4[cn])      : zero4;
        uint4 p2 = (cn + nw < ncyc) ? __ldg(&hist4[cn + nw]) : zero4;

        unsigned long long a1 = 0, b1 = 0;
        accum_cycle(h1, lane, s_emb, a1, b1);
        out2[(size_t)c * 32 + lane] = make_ulonglong2(a1, b1);

        const int c2 = c + nw;
        if (c2 < ncyc) {
            unsigned long long a2 = 0, b2 = 0;
            accum_cycle(h2, lane, s_emb, a2, b2);
            out2[(size_t)c2 * 32 + lane] = make_ulonglong2(a2, b2);
        }

        // Self-clean for the next launch/replay.
        if (lane == 0) {
            g_hist[c] = zero2;
            if (c2 < ncyc) g_hist[c2] = zero2;
        }

        h1 = p1; h2 = p2;
        c = cn;
    }
}

// ---------------------------------------------------------------------------
// Inputs (metadata order):
//   d_in[0]: x             int32 [500000]
//   d_in[1]: atom_to_cycle int32 [2, 2000000]  (row 0 = atom idx, row 1 = cycle idx)
//   d_in[2]: emb_weight    fp32  [28, 128]
// Output: fp32 [500000, 128]
// ---------------------------------------------------------------------------
extern "C" void kernel_launch(void* const* d_in, const int* in_sizes, int n_in,
                              void* d_out, int out_size)
{
    const int*   x   = (const int*)d_in[0];
    const int*   a2c = (const int*)d_in[1];
    const float* emb = (const float*)d_in[2];
    float*       out = (float*)d_out;

    const int n_inc = in_sizes[1] / 2;
    const int ncyc  = out_size / HIDDEN;

    k_scatter<<<1184, 256>>>(x, a2c, a2c + n_inc, n_inc);
    k_final<<<1184, 256>>>(emb, out, ncyc);
}

// round 14
// speedup vs baseline: 1.1745x; 1.0948x over previous
#include <cuda_runtime.h>

#define HIDDEN 128
#define NTYPES 28
#define MAX_CYCLES 500000

// Packed per-cycle type histogram: 2 x u64, 16 types/word, 4-bit nibbles
// (word = t>>4, nibble = t&15; nibbles 28-31 never touched).
// Zero at module load; k_final self-cleans after reading, so every replay
// sees zeros. Integer red-adds => deterministic.
__device__ ulonglong2 g_hist[MAX_CYCLES];   // 8 MB, L2-resident

// ---------------------------------------------------------------------------
// Scatter: one red.global.add.u64 per incidence. Index streams use evict-
// first loads so the hist (the only reused data) stays L2-resident.
// ---------------------------------------------------------------------------
__global__ void __launch_bounds__(256)
k_scatter(const int* __restrict__ x,
          const int* __restrict__ atom_row,
          const int* __restrict__ cyc_row, int n)
{
    const int n4 = n >> 2;
    int i = blockIdx.x * blockDim.x + threadIdx.x;
    const int stride = gridDim.x * blockDim.x;
    const int4* a4 = reinterpret_cast<const int4*>(atom_row);
    const int4* c4 = reinterpret_cast<const int4*>(cyc_row);

    for (; i < n4; i += stride) {
        int4 a = __ldcs(&a4[i]);        // streaming: evict-first
        int4 c = __ldcs(&c4[i]);
        int atoms[4] = {a.x, a.y, a.z, a.w};
        int cycs[4]  = {c.x, c.y, c.z, c.w};
#pragma unroll
        for (int k = 0; k < 4; k++) {
            int t = __ldg(&x[atoms[k]]);
            unsigned long long inc = 1ULL << ((t & 15) * 4);
            unsigned long long* dst =
                reinterpret_cast<unsigned long long*>(&g_hist[cycs[k]]) + (t >> 4);
            asm volatile("red.global.add.u64 [%0], %1;"
                         :: "l"(dst), "l"(inc) : "memory");
        }
    }
    for (int j = (n4 << 2) + blockIdx.x * blockDim.x + threadIdx.x; j < n;
         j += stride) {
        int t = __ldg(&x[__ldg(&atom_row[j])]);
        int cyc = __ldg(&cyc_row[j]);
        unsigned long long inc = 1ULL << ((t & 15) * 4);
        unsigned long long* dst =
            reinterpret_cast<unsigned long long*>(&g_hist[cyc]) + (t >> 4);
        asm volatile("red.global.add.u64 [%0], %1;"
                     :: "l"(dst), "l"(inc) : "memory");
    }
}

// ---------------------------------------------------------------------------
// Final: one warp per cycle (ILP-2). Lane l extracts count of type l from
// the uint4 hist view; ballot -> sparse type mask; per set bit: shfl count,
// LDS.128 of fp32 E[t] slice, 2x fma.rn.f32x2. Hist loads pinned in L2
// via createpolicy+cache_hint (evict_last); output stores streamed (st.cs).
// ---------------------------------------------------------------------------
__device__ __forceinline__ uint4 ld_hist_pin(const uint4* p)
{
    uint4 r;
    asm volatile(
        "{\n\t"
        ".reg .b64 pol;\n\t"
        "createpolicy.fractional.L2::evict_last.b64 pol, 1.0;\n\t"
        "ld.global.nc.L2::cache_hint.v4.u32 {%0,%1,%2,%3}, [%4], pol;\n\t"
        "}"
        : "=r"(r.x), "=r"(r.y), "=r"(r.z), "=r"(r.w) : "l"(p));
    return r;
}

__device__ __forceinline__ void st_out_cs(ulonglong2* p,
                                          unsigned long long a,
                                          unsigned long long b)
{
    asm volatile("st.global.cs.v2.b64 [%0], {%1, %2};"
                 :: "l"(p), "l"(a), "l"(b) : "memory");
}

__device__ __forceinline__ unsigned extract_cnt(uint4 h, int lane)
{
    unsigned lo16 = (lane & 8)  ? h.y : h.x;
    unsigned hi16 = (lane & 8)  ? h.w : h.z;
    unsigned w    = (lane & 16) ? hi16 : lo16;
    return (w >> ((lane & 7) * 4)) & 0xFu;
}

__device__ __forceinline__ void fma2(unsigned long long& acc,
                                     unsigned long long v,
                                     unsigned long long fc2)
{
    asm("fma.rn.f32x2 %0, %1, %2, %0;" : "+l"(acc) : "l"(v), "l"(fc2));
}

__device__ __forceinline__ unsigned long long pack2(float f)
{
    unsigned long long r;
    asm("mov.b64 %0, {%1, %1};" : "=l"(r) : "f"(f));
    return r;
}

__device__ __forceinline__ void accum_cycle(uint4 h, int lane,
                                            const float4* s_emb,
                                            unsigned long long& a,
                                            unsigned long long& b)
{
    unsigned cnt = extract_cnt(h, lane);
    float fcnt = (float)cnt;
    unsigned mask = __ballot_sync(0xFFFFFFFFu, cnt != 0u);
    while (mask) {
        int t = __ffs(mask) - 1;
        mask &= mask - 1;
        unsigned long long fc2 = pack2(__shfl_sync(0xFFFFFFFFu, fcnt, t));
        ulonglong2 v = *reinterpret_cast<const ulonglong2*>(&s_emb[t * 32 + lane]);
        fma2(a, v.x, fc2); fma2(b, v.y, fc2);
    }
}

__global__ void __launch_bounds__(256)
k_final(const float* __restrict__ emb, float* __restrict__ out, int ncyc)
{
    __shared__ float4 s_emb[NTYPES * 32];
    for (int i = threadIdx.x; i < NTYPES * 32; i += blockDim.x)
        s_emb[i] = reinterpret_cast<const float4*>(emb)[i];
    __syncthreads();

    const int lane = threadIdx.x & 31;
    const int warp = (blockIdx.x * blockDim.x + threadIdx.x) >> 5;
    const int nw   = (gridDim.x * blockDim.x) >> 5;
    ulonglong2* out2 = reinterpret_cast<ulonglong2*>(out);
    const uint4* hist4 = reinterpret_cast<const uint4*>(g_hist);
    const ulonglong2 zero2 = make_ulonglong2(0ULL, 0ULL);

    for (int c = warp; c < ncyc; c += 2 * nw) {
        const int c2 = c + nw;
        // Issue both broadcast hist loads up front (MLP=2), pinned in L2.
        uint4 h1 = ld_hist_pin(&hist4[c]);
        uint4 h2 = (c2 < ncyc) ? ld_hist_pin(&hist4[c2]) : make_uint4(0, 0, 0, 0);

        unsigned long long a1 = 0, b1 = 0;
        accum_cycle(h1, lane, s_emb, a1, b1);
        st_out_cs(&out2[(size_t)c * 32 + lane], a1, b1);

        if (c2 < ncyc) {
            unsigned long long a2 = 0, b2 = 0;
            accum_cycle(h2, lane, s_emb, a2, b2);
            st_out_cs(&out2[(size_t)c2 * 32 + lane], a2, b2);
        }

        // Self-clean for the next launch/replay.
        if (lane == 0) {
            g_hist[c] = zero2;
            if (c2 < ncyc) g_hist[c2] = zero2;
        }
    }
}

// ---------------------------------------------------------------------------
// Inputs (metadata order):
//   d_in[0]: x             int32 [500000]
//   d_in[1]: atom_to_cycle int32 [2, 2000000]  (row 0 = atom idx, row 1 = cycle idx)
//   d_in[2]: emb_weight    fp32  [28, 128]
// Output: fp32 [500000, 128]
// ---------------------------------------------------------------------------
extern "C" void kernel_launch(void* const* d_in, const int* in_sizes, int n_in,
                              void* d_out, int out_size)
{
    const int*   x   = (const int*)d_in[0];
    const int*   a2c = (const int*)d_in[1];
    const float* emb = (const float*)d_in[2];
    float*       out = (float*)d_out;

    const int n_inc = in_sizes[1] / 2;
    const int ncyc  = out_size / HIDDEN;

    k_scatter<<<1184, 256>>>(x, a2c, a2c + n_inc, n_inc);
    k_final<<<1184, 256>>>(emb, out, ncyc);
}